// round 2
// baseline (speedup 1.0000x reference)
#include <cuda_runtime.h>

// Problem constants
#define T_DIM 1024   // time axis (GEMM K)
#define N_QK  256    // q/k head dim
#define N_V   256    // v head dim
#define C_DIM 128    // channels (attention seq len)
#define BD    1024   // B * D independent attention problems
#define M_TOT (BD * C_DIM)  // 131072 projection rows

// Scratch for projected q, k, v (alloc-free rule: __device__ globals)
__device__ float g_q[(size_t)M_TOT * N_QK];
__device__ float g_k[(size_t)M_TOT * N_QK];
__device__ float g_v[(size_t)M_TOT * N_V];

// ---------------------------------------------------------------------------
// Kernel 1: Y[M,256] = X[M,1024] @ W[256,1024]^T + bias
// 128x128 block tile, BK=16, 256 threads, 8x8 microtile, float4 everywhere.
// sel picks destination (0=q, 1=k, 2=v).
// ---------------------------------------------------------------------------
__global__ void __launch_bounds__(256) gemm_qkv(
    const float* __restrict__ X, const float* __restrict__ W,
    const float* __restrict__ bias, int sel)
{
    __shared__ __align__(16) float Xs[16][132];
    __shared__ __align__(16) float Ws[16][132];

    float* __restrict__ Y = (sel == 0) ? g_q : (sel == 1) ? g_k : g_v;

    const int bm  = blockIdx.x;          // 0..1023 (row tile)
    const int bn  = blockIdx.y;          // 0..1    (col tile)
    const int tid = threadIdx.x;
    const int tn  = tid & 15;            // 0..15
    const int tm  = tid >> 4;            // 0..15
    const int lr  = tid >> 2;            // 0..63 (load row)
    const int lc  = (tid & 3) << 2;      // 0,4,8,12 (load col group)

    const float* Xblk = X + (size_t)bm * 128 * T_DIM;
    const float* Wblk = W + (size_t)bn * 128 * T_DIM;

    float acc[8][8];
#pragma unroll
    for (int i = 0; i < 8; i++)
#pragma unroll
        for (int j = 0; j < 8; j++) acc[i][j] = 0.0f;

    for (int k0 = 0; k0 < T_DIM; k0 += 16) {
        float4 xv0 = *(const float4*)(Xblk + (size_t)lr        * T_DIM + k0 + lc);
        float4 xv1 = *(const float4*)(Xblk + (size_t)(lr + 64) * T_DIM + k0 + lc);
        float4 wv0 = *(const float4*)(Wblk + (size_t)lr        * T_DIM + k0 + lc);
        float4 wv1 = *(const float4*)(Wblk + (size_t)(lr + 64) * T_DIM + k0 + lc);

        __syncthreads();   // previous iteration's compute done before overwrite
        Xs[lc + 0][lr]      = xv0.x; Xs[lc + 1][lr]      = xv0.y;
        Xs[lc + 2][lr]      = xv0.z; Xs[lc + 3][lr]      = xv0.w;
        Xs[lc + 0][lr + 64] = xv1.x; Xs[lc + 1][lr + 64] = xv1.y;
        Xs[lc + 2][lr + 64] = xv1.z; Xs[lc + 3][lr + 64] = xv1.w;
        Ws[lc + 0][lr]      = wv0.x; Ws[lc + 1][lr]      = wv0.y;
        Ws[lc + 2][lr]      = wv0.z; Ws[lc + 3][lr]      = wv0.w;
        Ws[lc + 0][lr + 64] = wv1.x; Ws[lc + 1][lr + 64] = wv1.y;
        Ws[lc + 2][lr + 64] = wv1.z; Ws[lc + 3][lr + 64] = wv1.w;
        __syncthreads();

#pragma unroll
        for (int kk = 0; kk < 16; kk++) {
            float4 a0 = *(const float4*)&Xs[kk][tm * 8];
            float4 a1 = *(const float4*)&Xs[kk][tm * 8 + 4];
            float4 b0 = *(const float4*)&Ws[kk][tn * 8];
            float4 b1 = *(const float4*)&Ws[kk][tn * 8 + 4];
            float am[8] = {a0.x, a0.y, a0.z, a0.w, a1.x, a1.y, a1.z, a1.w};
            float bv[8] = {b0.x, b0.y, b0.z, b0.w, b1.x, b1.y, b1.z, b1.w};
#pragma unroll
            for (int i = 0; i < 8; i++)
#pragma unroll
                for (int j = 0; j < 8; j++)
                    acc[i][j] = fmaf(am[i], bv[j], acc[i][j]);
        }
    }

    // Epilogue: add bias, store
    float bb[8];
#pragma unroll
    for (int j = 0; j < 8; j++) bb[j] = bias[bn * 128 + tn * 8 + j];

    float* Yblk = Y + (size_t)bm * 128 * 256 + bn * 128;
#pragma unroll
    for (int i = 0; i < 8; i++) {
        const int row = tm * 8 + i;
        float4 o0 = make_float4(acc[i][0] + bb[0], acc[i][1] + bb[1],
                                acc[i][2] + bb[2], acc[i][3] + bb[3]);
        float4 o1 = make_float4(acc[i][4] + bb[4], acc[i][5] + bb[5],
                                acc[i][6] + bb[6], acc[i][7] + bb[7]);
        *(float4*)(Yblk + (size_t)row * 256 + tn * 8)     = o0;
        *(float4*)(Yblk + (size_t)row * 256 + tn * 8 + 4) = o1;
    }
}

// ---------------------------------------------------------------------------
// Kernel 2: per-(b,d) attention. One CTA per bd.
//   S = q @ k^T / 16   (128x128, acc in regs -> smem)
//   softmax rows of S  (thread-per-row)
//   Z = S @ v          (two 128-col halves)
// Dynamic smem: S[128][129] + two 16x132 tiles = 82944 B
// ---------------------------------------------------------------------------
__global__ void __launch_bounds__(256) attn_kernel(float* __restrict__ out)
{
    extern __shared__ __align__(16) float smem[];
    float* S  = smem;                 // 128*129
    float* As = smem + 128 * 129;     // 16*132
    float* Bs = As + 16 * 132;        // 16*132

    const int bd = blockIdx.x;
    const float* qb = g_q + (size_t)bd * C_DIM * N_QK;
    const float* kb = g_k + (size_t)bd * C_DIM * N_QK;
    const float* vb = g_v + (size_t)bd * C_DIM * N_V;
    float* ob = out + (size_t)bd * C_DIM * N_V;

    const int tid = threadIdx.x;
    const int tn  = tid & 15;
    const int tm  = tid >> 4;
    const int lr  = tid >> 2;
    const int lc  = (tid & 3) << 2;

    // ---- Phase 1: S = q @ k^T ----
    float acc[8][8];
#pragma unroll
    for (int i = 0; i < 8; i++)
#pragma unroll
        for (int j = 0; j < 8; j++) acc[i][j] = 0.0f;

    for (int k0 = 0; k0 < N_QK; k0 += 16) {
        float4 q0 = *(const float4*)(qb + (size_t)lr        * N_QK + k0 + lc);
        float4 q1 = *(const float4*)(qb + (size_t)(lr + 64) * N_QK + k0 + lc);
        float4 kk0 = *(const float4*)(kb + (size_t)lr        * N_QK + k0 + lc);
        float4 kk1 = *(const float4*)(kb + (size_t)(lr + 64) * N_QK + k0 + lc);

        __syncthreads();
        As[(lc + 0) * 132 + lr]      = q0.x; As[(lc + 1) * 132 + lr]      = q0.y;
        As[(lc + 2) * 132 + lr]      = q0.z; As[(lc + 3) * 132 + lr]      = q0.w;
        As[(lc + 0) * 132 + lr + 64] = q1.x; As[(lc + 1) * 132 + lr + 64] = q1.y;
        As[(lc + 2) * 132 + lr + 64] = q1.z; As[(lc + 3) * 132 + lr + 64] = q1.w;
        Bs[(lc + 0) * 132 + lr]      = kk0.x; Bs[(lc + 1) * 132 + lr]      = kk0.y;
        Bs[(lc + 2) * 132 + lr]      = kk0.z; Bs[(lc + 3) * 132 + lr]      = kk0.w;
        Bs[(lc + 0) * 132 + lr + 64] = kk1.x; Bs[(lc + 1) * 132 + lr + 64] = kk1.y;
        Bs[(lc + 2) * 132 + lr + 64] = kk1.z; Bs[(lc + 3) * 132 + lr + 64] = kk1.w;
        __syncthreads();

#pragma unroll
        for (int kk = 0; kk < 16; kk++) {
            float4 a0 = *(const float4*)&As[kk * 132 + tm * 8];
            float4 a1 = *(const float4*)&As[kk * 132 + tm * 8 + 4];
            float4 b0 = *(const float4*)&Bs[kk * 132 + tn * 8];
            float4 b1 = *(const float4*)&Bs[kk * 132 + tn * 8 + 4];
            float am[8] = {a0.x, a0.y, a0.z, a0.w, a1.x, a1.y, a1.z, a1.w};
            float bv[8] = {b0.x, b0.y, b0.z, b0.w, b1.x, b1.y, b1.z, b1.w};
#pragma unroll
            for (int i = 0; i < 8; i++)
#pragma unroll
                for (int j = 0; j < 8; j++)
                    acc[i][j] = fmaf(am[i], bv[j], acc[i][j]);
        }
    }

    const float scale = 0.0625f;  // 1/sqrt(256)
#pragma unroll
    for (int i = 0; i < 8; i++)
#pragma unroll
        for (int j = 0; j < 8; j++)
            S[(size_t)(tm * 8 + i) * 129 + tn * 8 + j] = acc[i][j] * scale;
    __syncthreads();

    // ---- Phase 2: row softmax (thread t owns row t) ----
    if (tid < 128) {
        float* row = &S[(size_t)tid * 129];
        float m = -1e30f;
        for (int j = 0; j < 128; j++) m = fmaxf(m, row[j]);
        float s = 0.0f;
        for (int j = 0; j < 128; j++) { float e = __expf(row[j] - m); row[j] = e; s += e; }
        float inv = 1.0f / s;
        for (int j = 0; j < 128; j++) row[j] *= inv;
    }
    __syncthreads();

    // ---- Phase 3: Z = S @ v, two 128-col halves ----
#pragma unroll
    for (int h = 0; h < 2; h++) {
        float z[8][8];
#pragma unroll
        for (int i = 0; i < 8; i++)
#pragma unroll
            for (int j = 0; j < 8; j++) z[i][j] = 0.0f;

        for (int j0 = 0; j0 < 128; j0 += 16) {
            const int vr = tid >> 5;          // 0..7
            const int vc = (tid & 31) << 2;   // 0..124
            float4 v0 = *(const float4*)(vb + (size_t)(j0 + vr)     * N_V + h * 128 + vc);
            float4 v1 = *(const float4*)(vb + (size_t)(j0 + vr + 8) * N_V + h * 128 + vc);
            __syncthreads();
            *(float4*)&Bs[(vr)     * 132 + vc] = v0;
            *(float4*)&Bs[(vr + 8) * 132 + vc] = v1;
            __syncthreads();

#pragma unroll
            for (int jj = 0; jj < 16; jj++) {
                float a[8];
#pragma unroll
                for (int i = 0; i < 8; i++)
                    a[i] = S[(size_t)(tm * 8 + i) * 129 + j0 + jj];
                float4 b0 = *(const float4*)&Bs[jj * 132 + tn * 8];
                float4 b1 = *(const float4*)&Bs[jj * 132 + tn * 8 + 4];
                float bv[8] = {b0.x, b0.y, b0.z, b0.w, b1.x, b1.y, b1.z, b1.w};
#pragma unroll
                for (int i = 0; i < 8; i++)
#pragma unroll
                    for (int j = 0; j < 8; j++)
                        z[i][j] = fmaf(a[i], bv[j], z[i][j]);
            }
        }

#pragma unroll
        for (int i = 0; i < 8; i++) {
            float4 o0 = make_float4(z[i][0], z[i][1], z[i][2], z[i][3]);
            float4 o1 = make_float4(z[i][4], z[i][5], z[i][6], z[i][7]);
            *(float4*)(ob + (size_t)(tm * 8 + i) * N_V + h * 128 + tn * 8)     = o0;
            *(float4*)(ob + (size_t)(tm * 8 + i) * N_V + h * 128 + tn * 8 + 4) = o1;
        }
    }
}

// ---------------------------------------------------------------------------
extern "C" void kernel_launch(void* const* d_in, const int* in_sizes, int n_in,
                              void* d_out, int out_size)
{
    const float* x  = (const float*)d_in[0];
    const float* Wq = (const float*)d_in[1];
    const float* bq = (const float*)d_in[2];
    const float* Wk = (const float*)d_in[3];
    const float* bk = (const float*)d_in[4];
    const float* Wv = (const float*)d_in[5];
    const float* bv = (const float*)d_in[6];
    float* out = (float*)d_out;

    dim3 grid1(M_TOT / 128, 2);
    gemm_qkv<<<grid1, 256>>>(x, Wq, bq, 0);
    gemm_qkv<<<grid1, 256>>>(x, Wk, bk, 1);
    gemm_qkv<<<grid1, 256>>>(x, Wv, bv, 2);

    const size_t smem2 = (size_t)(128 * 129 + 2 * 16 * 132) * sizeof(float);
    cudaFuncSetAttribute(attn_kernel, cudaFuncAttributeMaxDynamicSharedMemorySize,
                         (int)smem2);
    attn_kernel<<<BD, 256, smem2>>>(out);
}